// round 3
// baseline (speedup 1.0000x reference)
#include <cuda_runtime.h>
#include <cstdint>
#include <math.h>

#define B_SZ  32
#define T_LEN 2048
#define I_DIM 128
#define H_DIM 256
#define N_TOK (B_SZ * T_LEN)   // 65536

// Scratch (device globals: allocation-free rule)
__device__ float g_xB[(size_t)N_TOK * H_DIM];   // 64 MB
__device__ float g_hs[(size_t)N_TOK * H_DIM];   // 64 MB

// ---------------------------------------------------------------------------
// helpers
// ---------------------------------------------------------------------------
__device__ __forceinline__ uint32_t smem_u32(const void* p) {
    uint32_t a;
    asm("{ .reg .u64 t; cvta.to.shared.u64 t, %1; cvt.u32.u64 %0, t; }"
        : "=r"(a) : "l"(p));
    return a;
}
__device__ __forceinline__ void fma2(unsigned long long& acc,
                                     unsigned long long a,
                                     unsigned long long b) {
    asm("fma.rn.f32x2 %0, %1, %2, %0;" : "+l"(acc) : "l"(a), "l"(b));
}
__device__ __forceinline__ float lo_f(unsigned long long u) {
    return __uint_as_float((unsigned)(u & 0xffffffffull));
}
__device__ __forceinline__ float hi_f(unsigned long long u) {
    return __uint_as_float((unsigned)(u >> 32));
}
__device__ __forceinline__ unsigned long long pack2(float l, float h) {
    return (unsigned long long)__float_as_uint(l) |
           ((unsigned long long)__float_as_uint(h) << 32);
}
__device__ __forceinline__ void mbar_wait(uint32_t mbar, uint32_t parity) {
    asm volatile(
        "{\n\t.reg .pred P;\n\t"
        "WAITLOOP_%=:\n\t"
        "mbarrier.try_wait.parity.acquire.cta.shared::cta.b64 P, [%0], %1, 0x989680;\n\t"
        "@P bra.uni WAITDONE_%=;\n\t"
        "bra.uni WAITLOOP_%=;\n\t"
        "WAITDONE_%=:\n\t}"
        :: "r"(mbar), "r"(parity) : "memory");
}

// ---------------------------------------------------------------------------
// fp32 tiled GEMM with f32x2 packed FMA: Y[M,N] = X[M,K] @ W[K,N]
// BM=128, BN=64, BK=16, 256 threads, 8x4 micro-tile (as 8x2 packed pairs).
// X staged in smem pre-duplicated as (x,x) 64-bit words.
// ---------------------------------------------------------------------------
__global__ void __launch_bounds__(256) gemm_kernel(const float* __restrict__ X,
                                                   const float* __restrict__ W,
                                                   float* __restrict__ Y,
                                                   int M, int K, int N) {
    __shared__ unsigned long long Xs2[16][128];   // (x,x) packed, 16 KB
    __shared__ float Ws[16][64];                  // 4 KB

    const int tid = threadIdx.x;
    const int m0 = blockIdx.x * 128;
    const int n0 = blockIdx.y * 64;
    const int tx = tid & 15;     // 0..15 -> col pair group (4 cols = 2 pairs)
    const int ty = tid >> 4;     // 0..15 -> 8 rows

    unsigned long long acc[8][2];
#pragma unroll
    for (int r = 0; r < 8; r++) { acc[r][0] = 0ull; acc[r][1] = 0ull; }

    const int lrow  = tid >> 1;          // 0..127
    const int lpart = (tid & 1) * 8;     // 0 or 8

    for (int kt = 0; kt < K; kt += 16) {
        // Load X tile [128 x 16], store transposed + duplicated
        const float* xp = X + (size_t)(m0 + lrow) * K + kt + lpart;
        float4 v0 = *(const float4*)(xp);
        float4 v1 = *(const float4*)(xp + 4);
        float xv[8] = {v0.x, v0.y, v0.z, v0.w, v1.x, v1.y, v1.z, v1.w};
#pragma unroll
        for (int i = 0; i < 8; i++)
            Xs2[lpart + i][lrow] = pack2(xv[i], xv[i]);

        // Load W tile [16 x 64]
        {
            const int wk = tid >> 4;
            const int wn = (tid & 15) * 4;
            float4 wv = *(const float4*)(W + (size_t)(kt + wk) * N + n0 + wn);
            *(float4*)&Ws[wk][wn] = wv;
        }
        __syncthreads();

#pragma unroll
        for (int k = 0; k < 16; k++) {
            double2 wd = *(const double2*)&Ws[k][tx * 4];
            unsigned long long w0 = __double_as_longlong(wd.x);
            unsigned long long w1 = __double_as_longlong(wd.y);
#pragma unroll
            for (int rr = 0; rr < 4; rr++) {
                double2 xd = *(const double2*)&Xs2[k][ty * 8 + rr * 2];
                unsigned long long x0 = __double_as_longlong(xd.x);
                unsigned long long x1 = __double_as_longlong(xd.y);
                fma2(acc[rr * 2][0], x0, w0);
                fma2(acc[rr * 2][1], x0, w1);
                fma2(acc[rr * 2 + 1][0], x1, w0);
                fma2(acc[rr * 2 + 1][1], x1, w1);
            }
        }
        __syncthreads();
    }

#pragma unroll
    for (int r = 0; r < 8; r++) {
        double2 o;
        o.x = __longlong_as_double(acc[r][0]);   // cols tx*4, tx*4+1
        o.y = __longlong_as_double(acc[r][1]);   // cols tx*4+2, tx*4+3
        *(double2*)&Y[(size_t)(m0 + ty * 8 + r) * N + n0 + tx * 4] = o;
    }
}

// ---------------------------------------------------------------------------
// Scan kernel: 2-CTA cluster per batch (64 CTAs total). Each CTA owns 128
// output columns. Thread (jl = tid>>2, c = tid&3): column rank*128+jl,
// k-window [c*64, c*64+64). A column chunk fully in registers as f32x2 pairs.
// h double-buffered in smem (padded quarters, 68 floats each); halves
// exchanged per step via cp.async.bulk.shared::cluster + mbarrier tx.
// ---------------------------------------------------------------------------
#define HPAD 68                       // floats per 64-value quarter (16B skew)
#define HBUF (4 * HPAD)               // 272 floats per buffer
#define HALF_BYTES (2 * HPAD * 4)     // 544 bytes per CTA half

__global__ void __launch_bounds__(512, 1) __cluster_dims__(2, 1, 1)
scan_kernel(const float* __restrict__ A) {
    __shared__ __align__(16) float sh_h[2][HBUF];
    __shared__ __align__(8) unsigned long long bars[2];

    const int tid = threadIdx.x;
    uint32_t rank;
    asm("mov.u32 %0, %%cluster_ctarank;" : "=r"(rank));
    const int b  = blockIdx.x >> 1;
    const int jl = tid >> 2;            // 0..127
    const int c  = tid & 3;             // 0..3
    const int col = (int)rank * 128 + jl;
    const int k0  = c * 64;

    // A column chunk into registers as packed (A[k], A[k+1]) pairs
    unsigned long long a2[32];
#pragma unroll
    for (int q = 0; q < 32; q++) {
        float fl = A[(size_t)(k0 + 2 * q) * H_DIM + col];
        float fh = A[(size_t)(k0 + 2 * q + 1) * H_DIM + col];
        a2[q] = pack2(fl, fh);
    }

    const uint32_t bar_u32[2] = { smem_u32(&bars[0]), smem_u32(&bars[1]) };
    if (tid == 0) {
        asm volatile("mbarrier.init.shared.b64 [%0], 1;" :: "r"(bar_u32[0]) : "memory");
        asm volatile("mbarrier.init.shared.b64 [%0], 1;" :: "r"(bar_u32[1]) : "memory");
    }
    // h0 = 0
    for (int i = tid; i < HBUF; i += 512) sh_h[0][i] = 0.f;
    __syncthreads();
    // cluster-wide: barriers + zeroed h visible before any peer traffic
    asm volatile("barrier.cluster.arrive.aligned;" ::: "memory");
    asm volatile("barrier.cluster.wait.aligned;" ::: "memory");

    // peer addresses (only tid 0 uses them)
    uint32_t my_src[2], peer_dst[2], peer_bar[2];
    {
        const uint32_t prank = rank ^ 1u;
#pragma unroll
        for (int i = 0; i < 2; i++) {
            uint32_t s = smem_u32(&sh_h[i][rank * 2 * HPAD]);
            my_src[i] = s;
            asm("mapa.shared::cluster.u32 %0, %1, %2;" : "=r"(peer_dst[i]) : "r"(s), "r"(prank));
            asm("mapa.shared::cluster.u32 %0, %1, %2;" : "=r"(peer_bar[i]) : "r"(bar_u32[i]), "r"(prank));
        }
    }

    const float* xB = g_xB + (size_t)b * T_LEN * H_DIM;
    float*       hs = g_hs + (size_t)b * T_LEN * H_DIM;
    const int wr_off = (int)rank * 2 * HPAD + (jl >> 6) * HPAD + (jl & 63);

    float xb_next = (c == 0) ? xB[col] : 0.f;

    for (int s = 0; s < T_LEN; s++) {
        const int rb = s & 1, wb = rb ^ 1;

        if (tid == 0 && s + 1 < T_LEN)
            asm volatile("mbarrier.arrive.expect_tx.shared.b64 _, [%0], %1;"
                         :: "r"(bar_u32[wb]), "r"((uint32_t)HALF_BYTES) : "memory");

        // partial dot: 16 broadcast LDS.128 + 32 packed FMAs
        const double2* hp = (const double2*)&sh_h[rb][c * HPAD];
        unsigned long long acc0 = 0ull, acc1 = 0ull;
#pragma unroll
        for (int q = 0; q < 16; q++) {
            double2 hv = hp[q];
            fma2(acc0, a2[2 * q],     (unsigned long long)__double_as_longlong(hv.x));
            fma2(acc1, a2[2 * q + 1], (unsigned long long)__double_as_longlong(hv.y));
        }
        float sum = (lo_f(acc0) + hi_f(acc0)) + (lo_f(acc1) + hi_f(acc1));
        sum += __shfl_xor_sync(0xffffffffu, sum, 1);
        sum += __shfl_xor_sync(0xffffffffu, sum, 2);

        if (c == 0) {
            float y = tanhf(sum + xb_next);
            sh_h[wb][wr_off] = y;
            hs[(size_t)s * H_DIM + col] = y;
            if (s + 1 < T_LEN) xb_next = xB[(size_t)(s + 1) * H_DIM + col];
        }
        __syncthreads();

        if (s + 1 < T_LEN) {
            if (tid == 0) {
                asm volatile("fence.proxy.async.shared::cta;" ::: "memory");
                asm volatile(
                    "cp.async.bulk.shared::cluster.shared::cta.mbarrier::complete_tx::bytes "
                    "[%0], [%1], %2, [%3];"
                    :: "r"(peer_dst[wb]), "r"(my_src[wb]),
                       "r"((uint32_t)HALF_BYTES), "r"(peer_bar[wb])
                    : "memory");
            }
            // wait for peer's half of buffer wb
            mbar_wait(bar_u32[wb], (uint32_t)((s >> 1) & 1));
        }
    }

    // no CTA may exit while peer DSMEM traffic could be in flight
    asm volatile("barrier.cluster.arrive.aligned;" ::: "memory");
    asm volatile("barrier.cluster.wait.aligned;" ::: "memory");
}

// ---------------------------------------------------------------------------
extern "C" void kernel_launch(void* const* d_in, const int* in_sizes, int n_in,
                              void* d_out, int out_size) {
    const float* x  = (const float*)d_in[0];   // [32,2048,128]
    const float* A  = (const float*)d_in[1];   // [256,256]
    const float* Bm = (const float*)d_in[2];   // [128,256]
    const float* C  = (const float*)d_in[3];   // [256,256]
    float* out = (float*)d_out;                // [32,2048,256]

    float* xBp = nullptr;
    float* hsp = nullptr;
    cudaGetSymbolAddress((void**)&xBp, g_xB);
    cudaGetSymbolAddress((void**)&hsp, g_hs);

    // 1) xB = x @ Bm : [65536,128] @ [128,256]
    gemm_kernel<<<dim3(N_TOK / 128, H_DIM / 64), 256>>>(x, Bm, xBp, N_TOK, I_DIM, H_DIM);
    // 2) sequential scan over T: 2-CTA cluster per batch (static __cluster_dims__)
    scan_kernel<<<B_SZ * 2, 512>>>(A);
    // 3) out = hs @ C : [65536,256] @ [256,256]
    gemm_kernel<<<dim3(N_TOK / 128, H_DIM / 64), 256>>>(hsp, C, out, N_TOK, H_DIM, H_DIM);
}